// round 3
// baseline (speedup 1.0000x reference)
#include <cuda_runtime.h>
#include <math.h>

#define Bb 32
#define Cc 256
#define Nn 4096
#define KD 64
#define HEADS 8
#define QD 512
#define OD 256

// Scratch (device globals: allocation-free per harness rules)
__device__ float g_kv[(size_t)Bb*128*Nn];          // rows 0..63 = k raw, 64..127 = v (64 MB)
__device__ float g_rowmax[Bb*KD];
__device__ float g_rowsum[Bb*KD];
__device__ float g_ctx_part[(size_t)Bb*16*KD*KD];  // split-n partials (8 MB)
__device__ float g_ctx[(size_t)Bb*KD*KD];
__device__ float g_M[(size_t)Bb*OD*QD];            // Wo folded with ctx (16.8 MB)

// K1: k,v projections.  grid (N/64, 2, B), 256 thr, 64x64 tile, 4x4 microtile
__global__ void __launch_bounds__(256) kv_proj_kernel(
    const float* __restrict__ x, const float* __restrict__ Wk, const float* __restrict__ bk,
    const float* __restrict__ Wv, const float* __restrict__ bv)
{
    __shared__ float As[64*33];
    __shared__ float Bs[32*64];
    int nt = blockIdx.x, rt = blockIdx.y, b = blockIdx.z;
    int n0 = nt*64;
    const float* W    = rt ? Wv : Wk;
    const float* bias = rt ? bv : bk;
    int tid = threadIdx.x;
    int ty = tid >> 4, tx = tid & 15;
    float acc[4][4] = {};
    for (int k0 = 0; k0 < Cc; k0 += 32) {
        for (int i = tid; i < 64*32; i += 256) {
            int r = i >> 5, kk = i & 31;
            As[r*33+kk] = W[r*Cc + k0 + kk];
        }
        for (int i = tid; i < 32*64; i += 256) {
            int kk = i >> 6, n = i & 63;
            Bs[kk*64+n] = x[((size_t)b*Cc + k0 + kk)*Nn + n0 + n];
        }
        __syncthreads();
        #pragma unroll
        for (int kk = 0; kk < 32; kk++) {
            float a[4], bb[4];
            #pragma unroll
            for (int i=0;i<4;i++) a[i] = As[(ty*4+i)*33+kk];
            #pragma unroll
            for (int j=0;j<4;j++) bb[j] = Bs[kk*64 + tx*4+j];
            #pragma unroll
            for (int i=0;i<4;i++)
                #pragma unroll
                for (int j=0;j<4;j++) acc[i][j] += a[i]*bb[j];
        }
        __syncthreads();
    }
    #pragma unroll
    for (int i=0;i<4;i++) {
        int r = ty*4+i;
        float bi = bias[r];
        #pragma unroll
        for (int j=0;j<4;j++)
            g_kv[((size_t)b*128 + rt*64 + r)*Nn + n0 + tx*4 + j] = acc[i][j] + bi;
    }
}

// K2: per-(b,d) softmax stats (max, sum-exp) over n=4096.  grid (64, B)
__global__ void __launch_bounds__(256) k_stats_kernel()
{
    int d = blockIdx.x, b = blockIdx.y;
    const float* row = g_kv + ((size_t)b*128 + d)*Nn;
    __shared__ float sred[256];
    int tid = threadIdx.x;
    float m = -1e30f;
    for (int i = tid; i < Nn; i += 256) m = fmaxf(m, row[i]);
    sred[tid] = m; __syncthreads();
    for (int s = 128; s > 0; s >>= 1) {
        if (tid < s) sred[tid] = fmaxf(sred[tid], sred[tid+s]);
        __syncthreads();
    }
    m = sred[0]; __syncthreads();
    float sum = 0.f;
    for (int i = tid; i < Nn; i += 256) sum += __expf(row[i]-m);
    sred[tid] = sum; __syncthreads();
    for (int s = 128; s > 0; s >>= 1) {
        if (tid < s) sred[tid] += sred[tid+s];
        __syncthreads();
    }
    if (tid == 0) { g_rowmax[b*KD+d] = m; g_rowsum[b*KD+d] = sred[0]; }
}

// K3a: ctx partials: ctx_p[b,s,d,e] = sum_{n in split} exp(k[d,n]-max_d) * v[e,n]
// grid (16 splits, B); 256 n per split, chunks of 64
__global__ void __launch_bounds__(256) ctx_part_kernel()
{
    __shared__ float ke[64*65];
    __shared__ float vt[64*65];
    int sp = blockIdx.x, b = blockIdx.y;
    int tid = threadIdx.x;
    int ty = tid >> 4, tx = tid & 15;
    float acc[4][4] = {};
    for (int nc = 0; nc < 256; nc += 64) {
        int gn0 = sp*256 + nc;
        for (int i = tid; i < 64*64; i += 256) {
            int r = i >> 6, n = i & 63;
            ke[r*65+n] = __expf(g_kv[((size_t)b*128 + r)*Nn + gn0 + n] - g_rowmax[b*KD + r]);
            vt[r*65+n] = g_kv[((size_t)b*128 + 64 + r)*Nn + gn0 + n];
        }
        __syncthreads();
        #pragma unroll
        for (int n = 0; n < 64; n++) {
            float a[4], bb[4];
            #pragma unroll
            for (int i=0;i<4;i++) a[i] = ke[(ty*4+i)*65+n];
            #pragma unroll
            for (int j=0;j<4;j++) bb[j] = vt[(tx*4+j)*65+n];
            #pragma unroll
            for (int i=0;i<4;i++)
                #pragma unroll
                for (int j=0;j<4;j++) acc[i][j] += a[i]*bb[j];
        }
        __syncthreads();
    }
    #pragma unroll
    for (int i=0;i<4;i++)
        #pragma unroll
        for (int j=0;j<4;j++)
            g_ctx_part[(((size_t)b*16 + sp)*KD + ty*4+i)*KD + tx*4+j] = acc[i][j];
}

// K3b: reduce 16 partials, divide by Z_d.  grid (B)
__global__ void __launch_bounds__(256) ctx_reduce_kernel()
{
    int b = blockIdx.x, tid = threadIdx.x;
    for (int i = tid; i < KD*KD; i += 256) {
        int d = i >> 6;
        float s = 0.f;
        #pragma unroll
        for (int p = 0; p < 16; p++) s += g_ctx_part[((size_t)b*16+p)*KD*KD + i];
        g_ctx[(size_t)b*KD*KD + i] = s / g_rowsum[b*KD + d];
    }
}

// K4: M[b,o,h*64+d] = sum_e Wo[o, h*64+e] * ctx[b,d,e].  grid (8 h, 4 otile, B)
__global__ void __launch_bounds__(256) m_kernel(const float* __restrict__ Wo)
{
    __shared__ float WoS[64*65];
    __shared__ float cS[64*65];
    int h = blockIdx.x, ot = blockIdx.y, b = blockIdx.z;
    int tid = threadIdx.x;
    int ty = tid >> 4, tx = tid & 15;
    for (int i = tid; i < 64*64; i += 256) {
        int r = i >> 6, e = i & 63;
        WoS[r*65+e] = Wo[(ot*64 + r)*QD + h*64 + e];
        cS[r*65+e]  = g_ctx[(size_t)b*KD*KD + r*64 + e];
    }
    __syncthreads();
    float acc[4][4] = {};
    #pragma unroll
    for (int e = 0; e < 64; e++) {
        float a[4], bb[4];
        #pragma unroll
        for (int i=0;i<4;i++) a[i] = WoS[(ty*4+i)*65+e];
        #pragma unroll
        for (int j=0;j<4;j++) bb[j] = cS[(tx*4+j)*65+e];
        #pragma unroll
        for (int i=0;i<4;i++)
            #pragma unroll
            for (int j=0;j<4;j++) acc[i][j] += a[i]*bb[j];
    }
    #pragma unroll
    for (int i=0;i<4;i++)
        #pragma unroll
        for (int j=0;j<4;j++)
            g_M[((size_t)b*OD + ot*64 + ty*4+i)*QD + h*64 + tx*4+j] = acc[i][j];
}

// K5: fused  q = Wq@x+bq  -> softmax over d (per head) -> out = M[b]@q_s + bo
// grid (N/32, B), 256 thr.  Dynamic smem: x[256][32] + q[512][32] + A[128][33] = 115200 B
__global__ void __launch_bounds__(256) fused_q_out_kernel(
    const float* __restrict__ x, const float* __restrict__ Wq, const float* __restrict__ bq,
    const float* __restrict__ bo, float* __restrict__ out)
{
    extern __shared__ float sm[];
    float* xs = sm;                      // [256][32]
    float* qs = sm + 256*32;             // [512][32]
    float* As = sm + 256*32 + 512*32;    // [128][33]
    int nt = blockIdx.x, b = blockIdx.y;
    int n0 = nt*32;
    int tid = threadIdx.x;
    int ty = tid >> 3, tx = tid & 7;     // 32 x 8 thread grid

    for (int i = tid; i < 256*32; i += 256) {
        int c = i >> 5, n = i & 31;
        xs[i] = x[((size_t)b*Cc + c)*Nn + n0 + n];
    }
    __syncthreads();

    // Phase A: q = Wq @ x + bq  (512 x 32, 4 row-blocks of 128)
    for (int rb = 0; rb < 4; rb++) {
        float acc[4][4] = {};
        for (int k0 = 0; k0 < Cc; k0 += 32) {
            for (int i = tid; i < 128*32; i += 256) {
                int r = i >> 5, kk = i & 31;
                As[r*33+kk] = Wq[(rb*128 + r)*Cc + k0 + kk];
            }
            __syncthreads();
            #pragma unroll
            for (int kk = 0; kk < 32; kk++) {
                float a[4], bb[4];
                #pragma unroll
                for (int i=0;i<4;i++) a[i] = As[(ty*4+i)*33+kk];
                #pragma unroll
                for (int j=0;j<4;j++) bb[j] = xs[(k0+kk)*32 + tx*4+j];
                #pragma unroll
                for (int i=0;i<4;i++)
                    #pragma unroll
                    for (int j=0;j<4;j++) acc[i][j] += a[i]*bb[j];
            }
            __syncthreads();
        }
        #pragma unroll
        for (int i=0;i<4;i++) {
            int r = rb*128 + ty*4+i;
            float bi = bq[r];
            #pragma unroll
            for (int j=0;j<4;j++) qs[r*32 + tx*4+j] = acc[i][j] + bi;
        }
        __syncthreads();
    }

    // Phase B: softmax over d (64) per (head, column). 8 heads * 32 cols = 256 threads
    {
        int h = tid >> 5, col = tid & 31;
        float m = -1e30f;
        for (int d = 0; d < 64; d++) m = fmaxf(m, qs[(h*64+d)*32 + col]);
        float s = 0.f;
        for (int d = 0; d < 64; d++) s += __expf(qs[(h*64+d)*32 + col] - m);
        float inv = 1.f / s;
        for (int d = 0; d < 64; d++)
            qs[(h*64+d)*32 + col] = __expf(qs[(h*64+d)*32 + col] - m) * inv;
    }
    __syncthreads();

    // Phase C: out = M[b] @ q_s + bo  (256 x 32, K = 512)
    for (int rb = 0; rb < 2; rb++) {
        float acc[4][4] = {};
        for (int k0 = 0; k0 < QD; k0 += 32) {
            for (int i = tid; i < 128*32; i += 256) {
                int r = i >> 5, kk = i & 31;
                As[r*33+kk] = g_M[((size_t)b*OD + rb*128 + r)*QD + k0 + kk];
            }
            __syncthreads();
            #pragma unroll
            for (int kk = 0; kk < 32; kk++) {
                float a[4], bb[4];
                #pragma unroll
                for (int i=0;i<4;i++) a[i] = As[(ty*4+i)*33+kk];
                #pragma unroll
                for (int j=0;j<4;j++) bb[j] = qs[(k0+kk)*32 + tx*4+j];
                #pragma unroll
                for (int i=0;i<4;i++)
                    #pragma unroll
                    for (int j=0;j<4;j++) acc[i][j] += a[i]*bb[j];
            }
            __syncthreads();
        }
        #pragma unroll
        for (int i=0;i<4;i++) {
            int r = rb*128 + ty*4+i;
            float bi = bo[r];
            #pragma unroll
            for (int j=0;j<4;j++)
                out[((size_t)b*OD + r)*Nn + n0 + tx*4+j] = acc[i][j] + bi;
        }
        __syncthreads();
    }
}

extern "C" void kernel_launch(void* const* d_in, const int* in_sizes, int n_in,
                              void* d_out, int out_size)
{
    const float* x  = (const float*)d_in[0];
    const float* Wq = (const float*)d_in[1];
    const float* bq = (const float*)d_in[2];
    const float* Wk = (const float*)d_in[3];
    const float* bk = (const float*)d_in[4];
    const float* Wv = (const float*)d_in[5];
    const float* bv = (const float*)d_in[6];
    const float* Wo = (const float*)d_in[7];
    const float* bo = (const float*)d_in[8];
    float* out = (float*)d_out;

    kv_proj_kernel<<<dim3(64,2,32), 256>>>(x, Wk, bk, Wv, bv);
    k_stats_kernel<<<dim3(64,32), 256>>>();
    ctx_part_kernel<<<dim3(16,32), 256>>>();
    ctx_reduce_kernel<<<32, 256>>>();
    m_kernel<<<dim3(8,4,32), 256>>>(Wo);

    cudaFuncSetAttribute(fused_q_out_kernel,
                         cudaFuncAttributeMaxDynamicSharedMemorySize, 115200);
    fused_q_out_kernel<<<dim3(128,32), 256, 115200>>>(x, Wq, bq, bo, out);
}

// round 4
// speedup vs baseline: 2.7075x; 2.7075x over previous
#include <cuda_runtime.h>
#include <math.h>

#define Bb 32
#define Cc 256
#define Nn 4096
#define KD 64
#define HEADS 8
#define QD 512
#define OD 256

// ---------------- scratch (device globals; allocation-free) ----------------
__device__ __align__(256) float g_kv[(size_t)Bb*128*Nn];     // rows 0..63 = exp(k), 64..127 = v
__device__ __align__(256) float g_rowsum[Bb*KD];
__device__ __align__(256) float g_ctx_part[(size_t)Bb*16*KD*KD];
__device__ __align__(256) float g_ctx[(size_t)Bb*KD*KD];
__device__ __align__(256) float g_M[(size_t)Bb*OD*QD];       // tf32-rounded
__device__ __align__(256) float g_Wqr[QD*Cc];                // tf32-rounded Wq
__device__ __align__(256) float g_Wkvr[128*Cc];              // tf32-rounded [Wk; Wv]

// ---------------- helpers ----------------
__device__ __forceinline__ unsigned tf32u(float x){
    unsigned u; asm("cvt.rna.tf32.f32 %0, %1;" : "=r"(u) : "f"(x)); return u;
}
__device__ __forceinline__ float tf32f(float x){ return __uint_as_float(tf32u(x)); }

__device__ __forceinline__ void mma8(float* d, const unsigned* a, const unsigned* b){
    asm volatile("mma.sync.aligned.m16n8k8.row.col.f32.tf32.tf32.f32 "
        "{%0,%1,%2,%3}, {%4,%5,%6,%7}, {%8,%9}, {%0,%1,%2,%3};"
        : "+f"(d[0]), "+f"(d[1]), "+f"(d[2]), "+f"(d[3])
        : "r"(a[0]), "r"(a[1]), "r"(a[2]), "r"(a[3]), "r"(b[0]), "r"(b[1]));
}

__device__ __forceinline__ void cpa16(float* smem_dst, const float* gsrc){
    unsigned s = (unsigned)__cvta_generic_to_shared(smem_dst);
    asm volatile("cp.async.cg.shared.global [%0], [%1], 16;" :: "r"(s), "l"(gsrc));
}
#define CP_COMMIT() asm volatile("cp.async.commit_group;")
#define CP_WAIT1()  asm volatile("cp.async.wait_group 1;")
#define CP_WAIT0()  asm volatile("cp.async.wait_group 0;")

// ---------------- K0: tf32-round weights ----------------
__global__ void __launch_bounds__(256) round_kernel(
    const float* __restrict__ Wq, const float* __restrict__ Wk, const float* __restrict__ Wv)
{
    int i = blockIdx.x*256 + threadIdx.x;
    if (i < QD*Cc) g_Wqr[i] = tf32f(Wq[i]);
    if (i < KD*Cc) { g_Wkvr[i] = tf32f(Wk[i]); g_Wkvr[KD*Cc + i] = tf32f(Wv[i]); }
}

// ---------------- K1: kv projection (tensor), writes exp(k) and v ----------------
// grid (64 ntiles, 32 b), 256 thr. smem: xs[256][72] + As[2][128][20] = 94208 B
__global__ void __launch_bounds__(256) kv_proj_mma(
    const float* __restrict__ x, const float* __restrict__ bk, const float* __restrict__ bv)
{
    extern __shared__ float sm1[];
    float* xs = sm1;                 // [256][72]
    float* As = sm1 + 256*72;        // [2][128][20]
    const int nt = blockIdx.x, b = blockIdx.y;
    const int n0 = nt*64;
    const int tid = threadIdx.x;
    const int warp = tid>>5, lane = tid&31;
    const int g = lane>>2, t4 = lane&3;
    const int wr = warp>>1, wc = warp&1;

    for (int i = tid; i < 256*16; i += 256) {
        int c = i>>4, v = i&15;
        float4 val = *(const float4*)(x + ((size_t)b*Cc + c)*Nn + n0 + v*4);
        float* d = xs + c*72 + v*4;
        d[0]=tf32f(val.x); d[1]=tf32f(val.y); d[2]=tf32f(val.z); d[3]=tf32f(val.w);
    }
    // prefetch chunk 0 (128 rows x 16 cols)
    #pragma unroll
    for (int j=0;j<2;j++){
        int s = tid + 256*j;            // 0..511
        int row = s>>2, q4 = s&3;
        cpa16(As + row*20 + q4*4, g_Wkvr + row*Cc + q4*4);
    }
    CP_COMMIT();

    float acc[2][4][4];
    #pragma unroll
    for (int a=0;a<2;a++)
      #pragma unroll
      for (int c=0;c<4;c++)
        #pragma unroll
        for (int k=0;k<4;k++) acc[a][c][k]=0.f;

    const int NK = 16;
    for (int ki=0; ki<NK; ki++){
        if (ki+1 < NK){
            float* dst = As + ((ki+1)&1)*2560;
            const float* src = g_Wkvr + (ki+1)*16;
            #pragma unroll
            for (int j=0;j<2;j++){
                int s = tid + 256*j;
                int row = s>>2, q4 = s&3;
                cpa16(dst + row*20 + q4*4, src + row*Cc + q4*4);
            }
            CP_COMMIT(); CP_WAIT1();
        } else CP_WAIT0();
        __syncthreads();
        const float* A0 = As + (ki&1)*2560 + wr*32*20;
        #pragma unroll
        for (int sub=0; sub<2; sub++){
            unsigned bf[4][2];
            const float* xb = xs + (ki*16 + sub*8 + t4)*72 + wc*32 + g;
            #pragma unroll
            for (int n8=0;n8<4;n8++){
                bf[n8][0] = __float_as_uint(xb[n8*8]);
                bf[n8][1] = __float_as_uint(xb[n8*8 + 4*72]);
            }
            #pragma unroll
            for (int mt=0;mt<2;mt++){
                unsigned af[4];
                const float* Ap = A0 + (mt*16 + g)*20 + sub*8 + t4;
                af[0]=__float_as_uint(Ap[0]);
                af[1]=__float_as_uint(Ap[8*20]);
                af[2]=__float_as_uint(Ap[4]);
                af[3]=__float_as_uint(Ap[8*20 + 4]);
                #pragma unroll
                for (int n8=0;n8<4;n8++) mma8(acc[mt][n8], af, bf[n8]);
            }
        }
        __syncthreads();
    }
    // epilogue: bias, exp for k-rows, store float2 pairs
    #pragma unroll
    for (int mt=0;mt<2;mt++){
        int r0 = wr*32 + mt*16 + g;
        int r1 = r0 + 8;
        bool isk = (r0 < 64);
        float bi0 = isk ? bk[r0] : bv[r0-64];
        float bi1 = isk ? bk[r1] : bv[r1-64];
        #pragma unroll
        for (int n8=0;n8<4;n8++){
            int c = n0 + wc*32 + n8*8 + 2*t4;
            float v00 = acc[mt][n8][0]+bi0, v01 = acc[mt][n8][1]+bi0;
            float v10 = acc[mt][n8][2]+bi1, v11 = acc[mt][n8][3]+bi1;
            if (isk){ v00=__expf(v00); v01=__expf(v01); v10=__expf(v10); v11=__expf(v11); }
            *(float2*)(g_kv + ((size_t)b*128 + r0)*Nn + c) = make_float2(v00, v01);
            *(float2*)(g_kv + ((size_t)b*128 + r1)*Nn + c) = make_float2(v10, v11);
        }
    }
}

// ---------------- K2: row sums of exp(k) ----------------
__global__ void __launch_bounds__(256) rowsum_kernel()
{
    int d = blockIdx.x, b = blockIdx.y;
    const float* row = g_kv + ((size_t)b*128 + d)*Nn;
    __shared__ float red[256];
    float s = 0.f;
    for (int i = threadIdx.x; i < Nn; i += 256) s += row[i];
    red[threadIdx.x] = s; __syncthreads();
    for (int st=128; st>0; st>>=1){
        if (threadIdx.x < st) red[threadIdx.x] += red[threadIdx.x+st];
        __syncthreads();
    }
    if (threadIdx.x == 0) g_rowsum[b*KD+d] = red[0];
}

// ---------------- K3a: ctx partials (exp(k) already stored) ----------------
__global__ void __launch_bounds__(256) ctx_part_kernel()
{
    __shared__ float ke[64*65];
    __shared__ float vt[64*65];
    int sp = blockIdx.x, b = blockIdx.y;
    int tid = threadIdx.x;
    int ty = tid >> 4, tx = tid & 15;
    float acc[4][4] = {};
    for (int nc = 0; nc < 256; nc += 64) {
        int gn0 = sp*256 + nc;
        for (int i = tid; i < 64*64; i += 256) {
            int r = i >> 6, n = i & 63;
            ke[r*65+n] = g_kv[((size_t)b*128 + r)*Nn + gn0 + n];
            vt[r*65+n] = g_kv[((size_t)b*128 + 64 + r)*Nn + gn0 + n];
        }
        __syncthreads();
        #pragma unroll
        for (int n = 0; n < 64; n++) {
            float a[4], bb[4];
            #pragma unroll
            for (int i=0;i<4;i++) a[i] = ke[(ty*4+i)*65+n];
            #pragma unroll
            for (int j=0;j<4;j++) bb[j] = vt[(tx*4+j)*65+n];
            #pragma unroll
            for (int i=0;i<4;i++)
                #pragma unroll
                for (int j=0;j<4;j++) acc[i][j] += a[i]*bb[j];
        }
        __syncthreads();
    }
    #pragma unroll
    for (int i=0;i<4;i++)
        #pragma unroll
        for (int j=0;j<4;j++)
            g_ctx_part[(((size_t)b*16 + sp)*KD + ty*4+i)*KD + tx*4+j] = acc[i][j];
}

// ---------------- K3b: reduce partials, divide by rowsum ----------------
__global__ void __launch_bounds__(256) ctx_reduce_kernel()
{
    int b = blockIdx.x, tid = threadIdx.x;
    for (int i = tid; i < KD*KD; i += 256) {
        int d = i >> 6;
        float s = 0.f;
        #pragma unroll
        for (int p = 0; p < 16; p++) s += g_ctx_part[((size_t)b*16+p)*KD*KD + i];
        g_ctx[(size_t)b*KD*KD + i] = s / g_rowsum[b*KD + d];
    }
}

// ---------------- K4: M = Wo folded with ctx, tf32-rounded ----------------
__global__ void __launch_bounds__(256) m_kernel(const float* __restrict__ Wo)
{
    __shared__ float WoS[64*65];
    __shared__ float cS[64*65];
    int h = blockIdx.x, ot = blockIdx.y, b = blockIdx.z;
    int tid = threadIdx.x;
    int ty = tid >> 4, tx = tid & 15;
    for (int i = tid; i < 64*64; i += 256) {
        int r = i >> 6, e = i & 63;
        WoS[r*65+e] = Wo[(ot*64 + r)*QD + h*64 + e];
        cS[r*65+e]  = g_ctx[(size_t)b*KD*KD + r*64 + e];
    }
    __syncthreads();
    float acc[4][4] = {};
    #pragma unroll
    for (int e = 0; e < 64; e++) {
        float a[4], bb[4];
        #pragma unroll
        for (int i=0;i<4;i++) a[i] = WoS[(ty*4+i)*65+e];
        #pragma unroll
        for (int j=0;j<4;j++) bb[j] = cS[(tx*4+j)*65+e];
        #pragma unroll
        for (int i=0;i<4;i++)
            #pragma unroll
            for (int j=0;j<4;j++) acc[i][j] += a[i]*bb[j];
    }
    #pragma unroll
    for (int i=0;i<4;i++)
        #pragma unroll
        for (int j=0;j<4;j++)
            g_M[((size_t)b*OD + ot*64 + ty*4+i)*QD + h*64 + tx*4+j] = tf32f(acc[i][j]);
}

// ---------------- K5: fused q-proj -> softmax(d) -> output GEMM (tensor) ----------------
// grid (64 ntiles, 32 b), 256 thr. smem: buf[512][72] + As[2][512][20] = 229376 B
__global__ void __launch_bounds__(256) fused_q_out_mma(
    const float* __restrict__ x, const float* __restrict__ bq,
    const float* __restrict__ bo, float* __restrict__ out)
{
    extern __shared__ float sm[];
    float* buf = sm;                 // phase A: xs rows 0..255; phase C: qs[512][72]
    float* As  = sm + 512*72;        // [2][512][20]
    const int nt = blockIdx.x, b = blockIdx.y;
    const int n0 = nt*64;
    const int tid = threadIdx.x;
    const int warp = tid>>5, lane = tid&31;
    const int g = lane>>2, t4 = lane&3;

    // x tile (256 x 64), tf32-rounded
    for (int i = tid; i < 256*16; i += 256) {
        int c = i>>4, v = i&15;
        float4 val = *(const float4*)(x + ((size_t)b*Cc + c)*Nn + n0 + v*4);
        float* d = buf + c*72 + v*4;
        d[0]=tf32f(val.x); d[1]=tf32f(val.y); d[2]=tf32f(val.z); d[3]=tf32f(val.w);
    }
    // prefetch Wq chunk 0 (512 rows x 16 cols)
    #pragma unroll
    for (int j=0;j<8;j++){
        int s = tid + 256*j;            // 0..2047
        int row = s>>2, q4 = s&3;
        cpa16(As + row*20 + q4*4, g_Wqr + row*Cc + q4*4);
    }
    CP_COMMIT();

    // ---- Phase A: q = Wq @ x ; warp == head, warp tile 64x64 ----
    float acc[4][8][4];
    #pragma unroll
    for (int a=0;a<4;a++)
      #pragma unroll
      for (int c=0;c<8;c++)
        #pragma unroll
        for (int k=0;k<4;k++) acc[a][c][k]=0.f;

    const int NKA = 16;
    for (int ki=0; ki<NKA; ki++){
        if (ki+1 < NKA){
            float* dst = As + ((ki+1)&1)*10240;
            const float* src = g_Wqr + (ki+1)*16;
            #pragma unroll
            for (int j=0;j<8;j++){
                int s = tid + 256*j;
                int row = s>>2, q4 = s&3;
                cpa16(dst + row*20 + q4*4, src + row*Cc + q4*4);
            }
            CP_COMMIT(); CP_WAIT1();
        } else CP_WAIT0();
        __syncthreads();
        const float* A0 = As + (ki&1)*10240 + warp*64*20;
        #pragma unroll
        for (int sub=0; sub<2; sub++){
            unsigned bf[8][2];
            const float* xb = buf + (ki*16 + sub*8 + t4)*72 + g;
            #pragma unroll
            for (int n8=0;n8<8;n8++){
                bf[n8][0] = __float_as_uint(xb[n8*8]);
                bf[n8][1] = __float_as_uint(xb[n8*8 + 4*72]);
            }
            #pragma unroll
            for (int mt=0;mt<4;mt++){
                unsigned af[4];
                const float* Ap = A0 + (mt*16 + g)*20 + sub*8 + t4;
                af[0]=__float_as_uint(Ap[0]);
                af[1]=__float_as_uint(Ap[8*20]);
                af[2]=__float_as_uint(Ap[4]);
                af[3]=__float_as_uint(Ap[8*20 + 4]);
                #pragma unroll
                for (int n8=0;n8<8;n8++) mma8(acc[mt][n8], af, bf[n8]);
            }
        }
        __syncthreads();
    }

    // ---- Phase B: bias + exp + softmax over kd (64 rows = this warp) ----
    #pragma unroll
    for (int mt=0;mt<4;mt++){
        float b0 = bq[warp*64 + mt*16 + g];
        float b1 = bq[warp*64 + mt*16 + g + 8];
        #pragma unroll
        for (int n8=0;n8<8;n8++){
            acc[mt][n8][0] = __expf(acc[mt][n8][0] + b0);
            acc[mt][n8][1] = __expf(acc[mt][n8][1] + b0);
            acc[mt][n8][2] = __expf(acc[mt][n8][2] + b1);
            acc[mt][n8][3] = __expf(acc[mt][n8][3] + b1);
        }
    }
    float inv[8][2];
    #pragma unroll
    for (int n8=0;n8<8;n8++){
        #pragma unroll
        for (int p=0;p<2;p++){
            float s = 0.f;
            #pragma unroll
            for (int mt=0;mt<4;mt++) s += acc[mt][n8][p] + acc[mt][n8][p+2];
            s += __shfl_xor_sync(0xffffffffu, s, 4);
            s += __shfl_xor_sync(0xffffffffu, s, 8);
            s += __shfl_xor_sync(0xffffffffu, s, 16);
            inv[n8][p] = 1.f/s;
        }
    }
    __syncthreads();   // everyone done reading xs
    #pragma unroll
    for (int mt=0;mt<4;mt++){
        int r = warp*64 + mt*16 + g;
        #pragma unroll
        for (int n8=0;n8<8;n8++){
            int c = n8*8 + 2*t4;
            buf[r*72 + c]       = tf32f(acc[mt][n8][0]*inv[n8][0]);
            buf[r*72 + c+1]     = tf32f(acc[mt][n8][1]*inv[n8][1]);
            buf[(r+8)*72 + c]   = tf32f(acc[mt][n8][2]*inv[n8][0]);
            buf[(r+8)*72 + c+1] = tf32f(acc[mt][n8][3]*inv[n8][1]);
        }
    }
    __syncthreads();

    // ---- Phase C: out = M[b] @ qs ; warp tile 64x32 ----
    const float* Mb = g_M + (size_t)b*OD*QD;
    #pragma unroll
    for (int j=0;j<4;j++){
        int s = tid + 256*j;            // 0..1023
        int row = s>>2, q4 = s&3;
        cpa16(As + row*20 + q4*4, Mb + row*QD + q4*4);
    }
    CP_COMMIT();

    float acc2[4][4][4];
    #pragma unroll
    for (int a=0;a<4;a++)
      #pragma unroll
      for (int c=0;c<4;c++)
        #pragma unroll
        for (int k=0;k<4;k++) acc2[a][c][k]=0.f;

    const int wr = warp>>1, wc = warp&1;
    const int NKC = 32;
    for (int ki=0; ki<NKC; ki++){
        if (ki+1 < NKC){
            float* dst = As + ((ki+1)&1)*10240;
            const float* src = Mb + (ki+1)*16;
            #pragma unroll
            for (int j=0;j<4;j++){
                int s = tid + 256*j;
                int row = s>>2, q4 = s&3;
                cpa16(dst + row*20 + q4*4, src + row*QD + q4*4);
            }
            CP_COMMIT(); CP_WAIT1();
        } else CP_WAIT0();
        __syncthreads();
        const float* A0 = As + (ki&1)*10240 + wr*64*20;
        #pragma unroll
        for (int sub=0; sub<2; sub++){
            unsigned bf[4][2];
            const float* qb = buf + (ki*16 + sub*8 + t4)*72 + wc*32 + g;
            #pragma unroll
            for (int n8=0;n8<4;n8++){
                bf[n8][0] = __float_as_uint(qb[n8*8]);
                bf[n8][1] = __float_as_uint(qb[n8*8 + 4*72]);
            }
            #pragma unroll
            for (int mt=0;mt<4;mt++){
                unsigned af[4];
                const float* Ap = A0 + (mt*16 + g)*20 + sub*8 + t4;
                af[0]=__float_as_uint(Ap[0]);
                af[1]=__float_as_uint(Ap[8*20]);
                af[2]=__float_as_uint(Ap[4]);
                af[3]=__float_as_uint(Ap[8*20 + 4]);
                #pragma unroll
                for (int n8=0;n8<4;n8++) mma8(acc2[mt][n8], af, bf[n8]);
            }
        }
        __syncthreads();
    }
    // epilogue
    #pragma unroll
    for (int mt=0;mt<4;mt++){
        int r0 = wr*64 + mt*16 + g;
        float bo0 = bo[r0], bo1 = bo[r0+8];
        #pragma unroll
        for (int n8=0;n8<4;n8++){
            int c = n0 + wc*32 + n8*8 + 2*t4;
            *(float2*)(out + ((size_t)b*OD + r0)*Nn + c) =
                make_float2(acc2[mt][n8][0]+bo0, acc2[mt][n8][1]+bo0);
            *(float2*)(out + ((size_t)b*OD + r0+8)*Nn + c) =
                make_float2(acc2[mt][n8][2]+bo1, acc2[mt][n8][3]+bo1);
        }
    }
}

// ---------------- launch ----------------
extern "C" void kernel_launch(void* const* d_in, const int* in_sizes, int n_in,
                              void* d_out, int out_size)
{
    const float* x  = (const float*)d_in[0];
    const float* Wq = (const float*)d_in[1];
    const float* bq = (const float*)d_in[2];
    const float* Wk = (const float*)d_in[3];
    const float* bk = (const float*)d_in[4];
    const float* Wv = (const float*)d_in[5];
    const float* bv = (const float*)d_in[6];
    const float* Wo = (const float*)d_in[7];
    const float* bo = (const float*)d_in[8];
    float* out = (float*)d_out;

    round_kernel<<<512, 256>>>(Wq, Wk, Wv);

    cudaFuncSetAttribute(kv_proj_mma, cudaFuncAttributeMaxDynamicSharedMemorySize, 94208);
    kv_proj_mma<<<dim3(64,32), 256, 94208>>>(x, bk, bv);

    rowsum_kernel<<<dim3(64,32), 256>>>();
    ctx_part_kernel<<<dim3(16,32), 256>>>();
    ctx_reduce_kernel<<<32, 256>>>();
    m_kernel<<<dim3(8,4,32), 256>>>(Wo);

    cudaFuncSetAttribute(fused_q_out_mma, cudaFuncAttributeMaxDynamicSharedMemorySize, 229376);
    fused_q_out_mma<<<dim3(64,32), 256, 229376>>>(x, bq, bo, out);
}

// round 6
// speedup vs baseline: 3.7130x; 1.3714x over previous
#include <cuda_runtime.h>
#include <cuda_fp16.h>
#include <math.h>

#define Bb 32
#define Cc 256
#define Nn 4096
#define KD 64
#define HEADS 8
#define QD 512
#define OD 256

// ---------------- scratch (device globals; allocation-free) ----------------
__device__ __align__(256) __half g_kvh[(size_t)Bb*128*Nn];   // rows 0..63 exp(k), 64..127 v (half)
__device__ __align__(256) float  g_rowsum[Bb*KD];
__device__ __align__(256) float  g_ctx_part[(size_t)Bb*16*KD*KD];
__device__ __align__(256) float  g_ctx[(size_t)Bb*KD*KD];
__device__ __align__(256) __half g_Mh[(size_t)Bb*OD*QD];     // folded Wo*ctx, half
__device__ __align__(256) float  g_Wqr[QD*Cc];               // tf32-rounded Wq
__device__ __align__(256) __half g_Wkvh[128*Cc];             // half [Wk; Wv]

// ---------------- helpers ----------------
__device__ __forceinline__ unsigned tf32u(float x){
    unsigned u; asm("cvt.rna.tf32.f32 %0, %1;" : "=r"(u) : "f"(x)); return u;
}
__device__ __forceinline__ float tf32f(float x){ return __uint_as_float(tf32u(x)); }

__device__ __forceinline__ void mma8(float* d, const unsigned* a, const unsigned* b){
    asm volatile("mma.sync.aligned.m16n8k8.row.col.f32.tf32.tf32.f32 "
        "{%0,%1,%2,%3}, {%4,%5,%6,%7}, {%8,%9}, {%0,%1,%2,%3};"
        : "+f"(d[0]), "+f"(d[1]), "+f"(d[2]), "+f"(d[3])
        : "r"(a[0]), "r"(a[1]), "r"(a[2]), "r"(a[3]), "r"(b[0]), "r"(b[1]));
}
__device__ __forceinline__ void mma16h(float* d, const unsigned* a, const unsigned* b){
    asm volatile("mma.sync.aligned.m16n8k16.row.col.f32.f16.f16.f32 "
        "{%0,%1,%2,%3}, {%4,%5,%6,%7}, {%8,%9}, {%0,%1,%2,%3};"
        : "+f"(d[0]), "+f"(d[1]), "+f"(d[2]), "+f"(d[3])
        : "r"(a[0]), "r"(a[1]), "r"(a[2]), "r"(a[3]), "r"(b[0]), "r"(b[1]));
}
__device__ __forceinline__ void cpa16(void* smem_dst, const void* gsrc){
    unsigned s = (unsigned)__cvta_generic_to_shared(smem_dst);
    asm volatile("cp.async.cg.shared.global [%0], [%1], 16;" :: "r"(s), "l"(gsrc));
}
#define CP_COMMIT() asm volatile("cp.async.commit_group;")
#define CP_WAIT1()  asm volatile("cp.async.wait_group 1;")
#define CP_WAIT0()  asm volatile("cp.async.wait_group 0;")

__device__ __forceinline__ unsigned ldh2(const __half* p){ return *(const unsigned*)p; }

// ---------------- K0: round/convert weights ----------------
__global__ void __launch_bounds__(256) round_kernel(
    const float* __restrict__ Wq, const float* __restrict__ Wk, const float* __restrict__ Wv)
{
    int i = blockIdx.x*256 + threadIdx.x;
    if (i < QD*Cc) g_Wqr[i] = tf32f(Wq[i]);
    if (i < KD*Cc) { g_Wkvh[i] = __float2half_rn(Wk[i]); g_Wkvh[KD*Cc + i] = __float2half_rn(Wv[i]); }
}

// ---------------- K1: kv projection (fp16 MMA) -> exp(k), v (half) ----------------
// grid (64 ntiles, 32 b), 256 thr. smem: xs half[64][264] + As half[2][128][40] = 54272 B
__global__ void __launch_bounds__(256) kv_proj_h(
    const float* __restrict__ x, const float* __restrict__ bk, const float* __restrict__ bv)
{
    extern __shared__ __half smk[];
    __half* xs = smk;                 // [n=64][c=264] (transposed, c contiguous)
    __half* As = smk + 64*264;        // [2][128][40]
    const int nt = blockIdx.x, b = blockIdx.y;
    const int n0 = nt*64;
    const int tid = threadIdx.x;
    const int warp = tid>>5, lane = tid&31;
    const int g = lane>>2, t4 = lane&3;
    const int wr = warp>>1, wc = warp&1;

    // load x tile [256 c][64 n], store transposed as half
    for (int i = tid; i < 256*16; i += 256) {
        int c = i>>4, n4 = (i&15)*4;
        float4 val = *(const float4*)(x + ((size_t)b*Cc + c)*Nn + n0 + n4);
        xs[(n4+0)*264 + c] = __float2half_rn(val.x);
        xs[(n4+1)*264 + c] = __float2half_rn(val.y);
        xs[(n4+2)*264 + c] = __float2half_rn(val.z);
        xs[(n4+3)*264 + c] = __float2half_rn(val.w);
    }
    // prefetch W chunk 0 (128 rows x 32 halves)
    #pragma unroll
    for (int j=0;j<2;j++){
        int s = tid + 256*j;             // 0..511
        int row = s>>2, seg = s&3;
        cpa16(As + row*40 + seg*8, g_Wkvh + row*Cc + seg*8);
    }
    CP_COMMIT();

    float acc[2][4][4];
    #pragma unroll
    for (int a=0;a<2;a++)
      #pragma unroll
      for (int c=0;c<4;c++)
        #pragma unroll
        for (int k=0;k<4;k++) acc[a][c][k]=0.f;

    const int NK = 8;   // 256 / 32
    for (int kc=0; kc<NK; kc++){
        if (kc+1 < NK){
            __half* dst = As + ((kc+1)&1)*5120;
            const __half* src = g_Wkvh + (kc+1)*32;
            #pragma unroll
            for (int j=0;j<2;j++){
                int s = tid + 256*j;
                int row = s>>2, seg = s&3;
                cpa16(dst + row*40 + seg*8, src + row*Cc + seg*8);
            }
            CP_COMMIT(); CP_WAIT1();
        } else CP_WAIT0();
        __syncthreads();
        const __half* A0 = As + (kc&1)*5120 + (wr*32)*40;
        #pragma unroll
        for (int sub=0; sub<2; sub++){
            int kl = sub*16 + t4*2;
            int kabs = kc*32 + kl;
            unsigned bf[4][2];
            #pragma unroll
            for (int n8=0;n8<4;n8++){
                int n = wc*32 + n8*8 + g;
                bf[n8][0] = ldh2(xs + n*264 + kabs);
                bf[n8][1] = ldh2(xs + n*264 + kabs + 8);
            }
            #pragma unroll
            for (int mt=0;mt<2;mt++){
                const __half* Ap = A0 + (mt*16 + g)*40 + kl;
                unsigned af[4];
                af[0] = ldh2(Ap);
                af[1] = ldh2(Ap + 8*40);
                af[2] = ldh2(Ap + 8);
                af[3] = ldh2(Ap + 8*40 + 8);
                #pragma unroll
                for (int n8=0;n8<4;n8++) mma16h(acc[mt][n8], af, bf[n8]);
            }
        }
        __syncthreads();
    }
    // epilogue: bias, exp for k-rows, store half2
    #pragma unroll
    for (int mt=0;mt<2;mt++){
        int r0 = wr*32 + mt*16 + g;
        int r1 = r0 + 8;
        bool isk = (r0 < 64);
        float bi0 = isk ? bk[r0] : bv[r0-64];
        float bi1 = isk ? bk[r1] : bv[r1-64];
        #pragma unroll
        for (int n8=0;n8<4;n8++){
            int c = n0 + wc*32 + n8*8 + 2*t4;
            float v00 = acc[mt][n8][0]+bi0, v01 = acc[mt][n8][1]+bi0;
            float v10 = acc[mt][n8][2]+bi1, v11 = acc[mt][n8][3]+bi1;
            if (isk){ v00=__expf(v00); v01=__expf(v01); v10=__expf(v10); v11=__expf(v11); }
            *(__half2*)(g_kvh + ((size_t)b*128 + r0)*Nn + c) = __floats2half2_rn(v00, v01);
            *(__half2*)(g_kvh + ((size_t)b*128 + r1)*Nn + c) = __floats2half2_rn(v10, v11);
        }
    }
}

// ---------------- K2: row sums of exp(k) ----------------
__global__ void __launch_bounds__(256) rowsum_kernel()
{
    int d = blockIdx.x, b = blockIdx.y;
    const __half2* row = (const __half2*)(g_kvh + ((size_t)b*128 + d)*Nn);
    __shared__ float red[256];
    float s = 0.f;
    for (int i = threadIdx.x; i < Nn/2; i += 256){
        float2 f = __half22float2(row[i]);
        s += f.x + f.y;
    }
    red[threadIdx.x] = s; __syncthreads();
    for (int st=128; st>0; st>>=1){
        if (threadIdx.x < st) red[threadIdx.x] += red[threadIdx.x+st];
        __syncthreads();
    }
    if (threadIdx.x == 0) g_rowsum[b*KD+d] = red[0];
}

// ---------------- K3a: ctx partials via fp16 MMA ----------------
// grid (16 splits, 32 b), 128 thr. smem: ts[2][128][72] half = 36864 B (16B aligned for cp.async)
__global__ void __launch_bounds__(128) ctx_part_h()
{
    __shared__ __align__(16) __half ts[2][128][72];
    const int sp = blockIdx.x, b = blockIdx.y;
    const int tid = threadIdx.x;
    const int warp = tid>>5, lane = tid&31;
    const int g = lane>>2, t4 = lane&3;
    const size_t base = (size_t)b*128*Nn + sp*256;

    // prefetch chunk 0: 128 rows x 64 halves
    #pragma unroll
    for (int j=0;j<8;j++){
        int s = tid + 128*j;             // 0..1023
        int row = s>>3, seg = s&7;
        cpa16(&ts[0][row][seg*8], g_kvh + base + (size_t)row*Nn + seg*8);
    }
    CP_COMMIT();

    float acc[8][4];
    #pragma unroll
    for (int c=0;c<8;c++)
      #pragma unroll
      for (int k=0;k<4;k++) acc[c][k]=0.f;

    for (int ch=0; ch<4; ch++){
        if (ch+1 < 4){
            #pragma unroll
            for (int j=0;j<8;j++){
                int s = tid + 128*j;
                int row = s>>3, seg = s&7;
                cpa16(&ts[(ch+1)&1][row][seg*8],
                      g_kvh + base + (size_t)row*Nn + (ch+1)*64 + seg*8);
            }
            CP_COMMIT(); CP_WAIT1();
        } else CP_WAIT0();
        __syncthreads();
        const int buf = ch&1;
        #pragma unroll
        for (int step=0; step<4; step++){
            int kl = step*16 + t4*2;
            unsigned af[4];
            int m = warp*16 + g;
            af[0] = ldh2(&ts[buf][m][kl]);
            af[1] = ldh2(&ts[buf][m+8][kl]);
            af[2] = ldh2(&ts[buf][m][kl+8]);
            af[3] = ldh2(&ts[buf][m+8][kl+8]);
            #pragma unroll
            for (int n8=0;n8<8;n8++){
                int e = n8*8 + g;
                unsigned bf[2];
                bf[0] = ldh2(&ts[buf][64+e][kl]);
                bf[1] = ldh2(&ts[buf][64+e][kl+8]);
                mma16h(acc[n8], af, bf);
            }
        }
        __syncthreads();
    }
    float* outp = g_ctx_part + ((size_t)b*16 + sp)*KD*KD;
    #pragma unroll
    for (int n8=0;n8<8;n8++){
        int r0 = warp*16 + g;
        int c  = n8*8 + 2*t4;
        *(float2*)(outp + r0*KD + c)     = make_float2(acc[n8][0], acc[n8][1]);
        *(float2*)(outp + (r0+8)*KD + c) = make_float2(acc[n8][2], acc[n8][3]);
    }
}

// ---------------- K3b: reduce partials, divide by rowsum ----------------
__global__ void __launch_bounds__(256) ctx_reduce_kernel()
{
    int b = blockIdx.x, tid = threadIdx.x;
    for (int i = tid; i < KD*KD; i += 256) {
        int d = i >> 6;
        float s = 0.f;
        #pragma unroll
        for (int p = 0; p < 16; p++) s += g_ctx_part[((size_t)b*16+p)*KD*KD + i];
        g_ctx[(size_t)b*KD*KD + i] = s / g_rowsum[b*KD + d];
    }
}

// ---------------- K4: M = Wo folded with ctx -> half ----------------
__global__ void __launch_bounds__(256) m_kernel(const float* __restrict__ Wo)
{
    __shared__ float WoS[64*65];
    __shared__ float cS[64*65];
    int h = blockIdx.x, ot = blockIdx.y, b = blockIdx.z;
    int tid = threadIdx.x;
    int ty = tid >> 4, tx = tid & 15;
    for (int i = tid; i < 64*64; i += 256) {
        int r = i >> 6, e = i & 63;
        WoS[r*65+e] = Wo[(ot*64 + r)*QD + h*64 + e];
        cS[r*65+e]  = g_ctx[(size_t)b*KD*KD + r*64 + e];
    }
    __syncthreads();
    float acc[4][4] = {};
    #pragma unroll
    for (int e = 0; e < 64; e++) {
        float a[4], bb[4];
        #pragma unroll
        for (int i=0;i<4;i++) a[i] = WoS[(ty*4+i)*65+e];
        #pragma unroll
        for (int j=0;j<4;j++) bb[j] = cS[(tx*4+j)*65+e];
        #pragma unroll
        for (int i=0;i<4;i++)
            #pragma unroll
            for (int j=0;j<4;j++) acc[i][j] += a[i]*bb[j];
    }
    #pragma unroll
    for (int i=0;i<4;i++)
        #pragma unroll
        for (int j=0;j<4;j++)
            g_Mh[((size_t)b*OD + ot*64 + ty*4+i)*QD + h*64 + tx*4+j] = __float2half_rn(acc[i][j]);
}

// ---------------- K5: fused q-proj(tf32) -> softmax(d) -> out GEMM (fp16) ----------------
// grid (64, 32), 256 thr. smem: xs f32[256][72] (aliased by qs half[64][520]) + As f32[2][512][20]
// (aliased by Ms half[2][256][40]) = 73728 + 81920 = 155648 B
__global__ void __launch_bounds__(256) fused_q_out_mma(
    const float* __restrict__ x, const float* __restrict__ bq,
    const float* __restrict__ bo, float* __restrict__ out)
{
    extern __shared__ float sm[];
    float*  xs  = sm;                   // [256][72] f32 (phase A)
    __half* qs  = (__half*)sm;          // [64][520] half (phase B/C), aliases xs
    float*  Asf = sm + 256*72;          // [2][512][20] f32 (phase A)
    __half* Msh = (__half*)Asf;         // [2][256][40] half (phase C), aliases Asf
    const int nt = blockIdx.x, b = blockIdx.y;
    const int n0 = nt*64;
    const int tid = threadIdx.x;
    const int warp = tid>>5, lane = tid&31;
    const int g = lane>>2, t4 = lane&3;

    // x tile (256 x 64), tf32-rounded
    for (int i = tid; i < 256*16; i += 256) {
        int c = i>>4, v = i&15;
        float4 val = *(const float4*)(x + ((size_t)b*Cc + c)*Nn + n0 + v*4);
        float* d = xs + c*72 + v*4;
        d[0]=tf32f(val.x); d[1]=tf32f(val.y); d[2]=tf32f(val.z); d[3]=tf32f(val.w);
    }
    // prefetch Wq chunk 0 (512 rows x 16 f32)
    #pragma unroll
    for (int j=0;j<8;j++){
        int s = tid + 256*j;
        int row = s>>2, q4 = s&3;
        cpa16(Asf + row*20 + q4*4, g_Wqr + row*Cc + q4*4);
    }
    CP_COMMIT();

    // ---- Phase A (tf32): q = Wq @ x ; warp == head, warp tile 64x64 ----
    float acc[4][8][4];
    #pragma unroll
    for (int a=0;a<4;a++)
      #pragma unroll
      for (int c=0;c<8;c++)
        #pragma unroll
        for (int k=0;k<4;k++) acc[a][c][k]=0.f;

    const int NKA = 16;
    for (int ki=0; ki<NKA; ki++){
        if (ki+1 < NKA){
            float* dst = Asf + ((ki+1)&1)*10240;
            const float* src = g_Wqr + (ki+1)*16;
            #pragma unroll
            for (int j=0;j<8;j++){
                int s = tid + 256*j;
                int row = s>>2, q4 = s&3;
                cpa16(dst + row*20 + q4*4, src + row*Cc + q4*4);
            }
            CP_COMMIT(); CP_WAIT1();
        } else CP_WAIT0();
        __syncthreads();
        const float* A0 = Asf + (ki&1)*10240 + warp*64*20;
        #pragma unroll
        for (int sub=0; sub<2; sub++){
            unsigned bf[8][2];
            const float* xb = xs + (ki*16 + sub*8 + t4)*72 + g;
            #pragma unroll
            for (int n8=0;n8<8;n8++){
                bf[n8][0] = __float_as_uint(xb[n8*8]);
                bf[n8][1] = __float_as_uint(xb[n8*8 + 4*72]);
            }
            #pragma unroll
            for (int mt=0;mt<4;mt++){
                unsigned af[4];
                const float* Ap = A0 + (mt*16 + g)*20 + sub*8 + t4;
                af[0]=__float_as_uint(Ap[0]);
                af[1]=__float_as_uint(Ap[8*20]);
                af[2]=__float_as_uint(Ap[4]);
                af[3]=__float_as_uint(Ap[8*20 + 4]);
                #pragma unroll
                for (int n8=0;n8<8;n8++) mma8(acc[mt][n8], af, bf[n8]);
            }
        }
        __syncthreads();
    }

    // ---- Phase B: bias + exp + softmax over kd (this warp = one head) ----
    #pragma unroll
    for (int mt=0;mt<4;mt++){
        float b0 = bq[warp*64 + mt*16 + g];
        float b1 = bq[warp*64 + mt*16 + g + 8];
        #pragma unroll
        for (int n8=0;n8<8;n8++){
            acc[mt][n8][0] = __expf(acc[mt][n8][0] + b0);
            acc[mt][n8][1] = __expf(acc[mt][n8][1] + b0);
            acc[mt][n8][2] = __expf(acc[mt][n8][2] + b1);
            acc[mt][n8][3] = __expf(acc[mt][n8][3] + b1);
        }
    }
    float inv[8][2];
    #pragma unroll
    for (int n8=0;n8<8;n8++){
        #pragma unroll
        for (int p=0;p<2;p++){
            float s = 0.f;
            #pragma unroll
            for (int mt=0;mt<4;mt++) s += acc[mt][n8][p] + acc[mt][n8][p+2];
            s += __shfl_xor_sync(0xffffffffu, s, 4);
            s += __shfl_xor_sync(0xffffffffu, s, 8);
            s += __shfl_xor_sync(0xffffffffu, s, 16);
            inv[n8][p] = 1.f/s;
        }
    }
    __syncthreads();   // all warps done reading xs & Asf
    // write q_s transposed into qs[n][k] as half
    #pragma unroll
    for (int mt=0;mt<4;mt++){
        int k0 = warp*64 + mt*16 + g;
        #pragma unroll
        for (int n8=0;n8<8;n8++){
            int n = n8*8 + 2*t4;
            qs[n*520 + k0]       = __float2half_rn(acc[mt][n8][0]*inv[n8][0]);
            qs[(n+1)*520 + k0]   = __float2half_rn(acc[mt][n8][1]*inv[n8][1]);
            qs[n*520 + k0+8]     = __float2half_rn(acc[mt][n8][2]*inv[n8][0]);
            qs[(n+1)*520 + k0+8] = __float2half_rn(acc[mt][n8][3]*inv[n8][1]);
        }
    }
    __syncthreads();

    // ---- Phase C (fp16): out = M[b] @ qs ; M is 256 rows x 512 cols ----
    const __half* Mb = g_Mh + (size_t)b*OD*QD;
    // stage k-chunk 0: 256 rows x 32 halves
    #pragma unroll
    for (int j=0;j<4;j++){
        int s = tid + 256*j;            // 0..1023
        int row = s>>2, seg = s&3;
        cpa16(Msh + row*40 + seg*8, Mb + row*QD + seg*8);
    }
    CP_COMMIT();

    float acc2[4][4][4];
    #pragma unroll
    for (int a=0;a<4;a++)
      #pragma unroll
      for (int c=0;c<4;c++)
        #pragma unroll
        for (int k=0;k<4;k++) acc2[a][c][k]=0.f;

    const int wr = warp>>1, wc = warp&1;
    const int NKC = 16;                  // 512 / 32
    for (int ki=0; ki<NKC; ki++){
        if (ki+1 < NKC){
            __half* dst = Msh + ((ki+1)&1)*10240;
            const __half* src = Mb + (ki+1)*32;
            #pragma unroll
            for (int j=0;j<4;j++){
                int s = tid + 256*j;
                int row = s>>2, seg = s&3;
                cpa16(dst + row*40 + seg*8, src + row*QD + seg*8);
            }
            CP_COMMIT(); CP_WAIT1();
        } else CP_WAIT0();
        __syncthreads();
        const __half* A0 = Msh + (ki&1)*10240 + (wr*64)*40;
        #pragma unroll
        for (int sub=0; sub<2; sub++){
            int kl = sub*16 + t4*2;
            int kabs = ki*32 + kl;
            unsigned bf[4][2];
            #pragma unroll
            for (int n8=0;n8<4;n8++){
                int n = wc*32 + n8*8 + g;
                bf[n8][0] = ldh2(qs + n*520 + kabs);
                bf[n8][1] = ldh2(qs + n*520 + kabs + 8);
            }
            #pragma unroll
            for (int mt=0;mt<4;mt++){
                const __half* Ap = A0 + (mt*16 + g)*40 + kl;
                unsigned af[4];
                af[0] = ldh2(Ap);
                af[1] = ldh2(Ap + 8*40);
                af[2] = ldh2(Ap + 8);
                af[3] = ldh2(Ap + 8*40 + 8);
                #pragma unroll
                for (int n8=0;n8<4;n8++) mma16h(acc2[mt][n8], af, bf[n8]);
            }
        }
        __syncthreads();
    }
    // epilogue
    #pragma unroll
    for (int mt=0;mt<4;mt++){
        int r0 = wr*64 + mt*16 + g;
        float bo0 = bo[r0], bo1 = bo[r0+8];
        #pragma unroll
        for (int n8=0;n8<4;n8++){
            int c = n0 + wc*32 + n8*8 + 2*t4;
            *(float2*)(out + ((size_t)b*OD + r0)*Nn + c) =
                make_float2(acc2[mt][n8][0]+bo0, acc2[mt][n8][1]+bo0);
            *(float2*)(out + ((size_t)b*OD + r0+8)*Nn + c) =
                make_float2(acc2[mt][n8][2]+bo1, acc2[mt][n8][3]+bo1);
        }
    }
}

// ---------------- launch ----------------
extern "C" void kernel_launch(void* const* d_in, const int* in_sizes, int n_in,
                              void* d_out, int out_size)
{
    const float* x  = (const float*)d_in[0];
    const float* Wq = (const float*)d_in[1];
    const float* bq = (const float*)d_in[2];
    const float* Wk = (const float*)d_in[3];
    const float* bk = (const float*)d_in[4];
    const float* Wv = (const float*)d_in[5];
    const float* bv = (const float*)d_in[6];
    const float* Wo = (const float*)d_in[7];
    const float* bo = (const float*)d_in[8];
    float* out = (float*)d_out;

    round_kernel<<<512, 256>>>(Wq, Wk, Wv);

    cudaFuncSetAttribute(kv_proj_h, cudaFuncAttributeMaxDynamicSharedMemorySize, 54272);
    kv_proj_h<<<dim3(64,32), 256, 54272>>>(x, bk, bv);

    rowsum_kernel<<<dim3(64,32), 256>>>();
    ctx_part_h<<<dim3(16,32), 128>>>();
    ctx_reduce_kernel<<<32, 256>>>();
    m_kernel<<<dim3(8,4,32), 256>>>(Wo);

    cudaFuncSetAttribute(fused_q_out_mma, cudaFuncAttributeMaxDynamicSharedMemorySize, 155648);
    fused_q_out_mma<<<dim3(64,32), 256, 155648>>>(x, bq, bo, out);
}

// round 7
// speedup vs baseline: 4.4767x; 1.2057x over previous
#include <cuda_runtime.h>
#include <cuda_fp16.h>
#include <math.h>

#define Bb 32
#define Cc 256
#define Nn 4096
#define KD 64
#define HEADS 8
#define QD 512
#define OD 256

// ---------------- scratch (device globals; allocation-free) ----------------
__device__ __align__(256) __half g_kvh[(size_t)Bb*128*Nn];   // rows 0..63 exp(k), 64..127 v (half)
__device__ __align__(256) float  g_rowsum[Bb*KD];
__device__ __align__(256) float  g_ctx_part[(size_t)Bb*16*KD*KD];
__device__ __align__(256) float  g_ctx[(size_t)Bb*KD*KD];
__device__ __align__(256) __half g_Mh[(size_t)Bb*OD*QD];     // folded Wo*ctx, half
__device__ __align__(256) __half g_Wqh[QD*Cc];               // half Wq
__device__ __align__(256) __half g_Wkvh[128*Cc];             // half [Wk; Wv]

// ---------------- helpers ----------------
__device__ __forceinline__ void mma16h(float* d, const unsigned* a, const unsigned* b){
    asm volatile("mma.sync.aligned.m16n8k16.row.col.f32.f16.f16.f32 "
        "{%0,%1,%2,%3}, {%4,%5,%6,%7}, {%8,%9}, {%0,%1,%2,%3};"
        : "+f"(d[0]), "+f"(d[1]), "+f"(d[2]), "+f"(d[3])
        : "r"(a[0]), "r"(a[1]), "r"(a[2]), "r"(a[3]), "r"(b[0]), "r"(b[1]));
}
__device__ __forceinline__ void cpa16(void* smem_dst, const void* gsrc){
    unsigned s = (unsigned)__cvta_generic_to_shared(smem_dst);
    asm volatile("cp.async.cg.shared.global [%0], [%1], 16;" :: "r"(s), "l"(gsrc));
}
#define CP_COMMIT() asm volatile("cp.async.commit_group;")
#define CP_WAIT1()  asm volatile("cp.async.wait_group 1;")
#define CP_WAIT0()  asm volatile("cp.async.wait_group 0;")

__device__ __forceinline__ unsigned ldh2(const __half* p){ return *(const unsigned*)p; }

// ---------------- K0: convert weights to half ----------------
__global__ void __launch_bounds__(256) round_kernel(
    const float* __restrict__ Wq, const float* __restrict__ Wk, const float* __restrict__ Wv)
{
    int i = blockIdx.x*256 + threadIdx.x;
    if (i < QD*Cc) g_Wqh[i] = __float2half_rn(Wq[i]);
    if (i < KD*Cc) { g_Wkvh[i] = __float2half_rn(Wk[i]); g_Wkvh[KD*Cc + i] = __float2half_rn(Wv[i]); }
}

// ---------------- K1: kv projection (fp16 MMA) -> exp(k), v (half) ----------------
// grid (64 ntiles, 32 b), 256 thr. smem: xs half[64][264] + As half[2][128][40] = 54272 B
__global__ void __launch_bounds__(256) kv_proj_h(
    const float* __restrict__ x, const float* __restrict__ bk, const float* __restrict__ bv)
{
    extern __shared__ __half smk[];
    __half* xs = smk;                 // [n=64][c=264] (transposed, c contiguous)
    __half* As = smk + 64*264;        // [2][128][40]
    const int nt = blockIdx.x, b = blockIdx.y;
    const int n0 = nt*64;
    const int tid = threadIdx.x;
    const int warp = tid>>5, lane = tid&31;
    const int g = lane>>2, t4 = lane&3;
    const int wr = warp>>1, wc = warp&1;

    // load x tile [256 c][64 n], store transposed as half
    for (int i = tid; i < 256*16; i += 256) {
        int c = i>>4, n4 = (i&15)*4;
        float4 val = *(const float4*)(x + ((size_t)b*Cc + c)*Nn + n0 + n4);
        xs[(n4+0)*264 + c] = __float2half_rn(val.x);
        xs[(n4+1)*264 + c] = __float2half_rn(val.y);
        xs[(n4+2)*264 + c] = __float2half_rn(val.z);
        xs[(n4+3)*264 + c] = __float2half_rn(val.w);
    }
    // prefetch W chunk 0 (128 rows x 32 halves)
    #pragma unroll
    for (int j=0;j<2;j++){
        int s = tid + 256*j;             // 0..511
        int row = s>>2, seg = s&3;
        cpa16(As + row*40 + seg*8, g_Wkvh + row*Cc + seg*8);
    }
    CP_COMMIT();

    float acc[2][4][4];
    #pragma unroll
    for (int a=0;a<2;a++)
      #pragma unroll
      for (int c=0;c<4;c++)
        #pragma unroll
        for (int k=0;k<4;k++) acc[a][c][k]=0.f;

    const int NK = 8;   // 256 / 32
    for (int kc=0; kc<NK; kc++){
        if (kc+1 < NK){
            __half* dst = As + ((kc+1)&1)*5120;
            const __half* src = g_Wkvh + (kc+1)*32;
            #pragma unroll
            for (int j=0;j<2;j++){
                int s = tid + 256*j;
                int row = s>>2, seg = s&3;
                cpa16(dst + row*40 + seg*8, src + row*Cc + seg*8);
            }
            CP_COMMIT(); CP_WAIT1();
        } else CP_WAIT0();
        __syncthreads();
        const __half* A0 = As + (kc&1)*5120 + (wr*32)*40;
        #pragma unroll
        for (int sub=0; sub<2; sub++){
            int kl = sub*16 + t4*2;
            int kabs = kc*32 + kl;
            unsigned bf[4][2];
            #pragma unroll
            for (int n8=0;n8<4;n8++){
                int n = wc*32 + n8*8 + g;
                bf[n8][0] = ldh2(xs + n*264 + kabs);
                bf[n8][1] = ldh2(xs + n*264 + kabs + 8);
            }
            #pragma unroll
            for (int mt=0;mt<2;mt++){
                const __half* Ap = A0 + (mt*16 + g)*40 + kl;
                unsigned af[4];
                af[0] = ldh2(Ap);
                af[1] = ldh2(Ap + 8*40);
                af[2] = ldh2(Ap + 8);
                af[3] = ldh2(Ap + 8*40 + 8);
                #pragma unroll
                for (int n8=0;n8<4;n8++) mma16h(acc[mt][n8], af, bf[n8]);
            }
        }
        __syncthreads();
    }
    // epilogue: bias, exp for k-rows, store half2
    #pragma unroll
    for (int mt=0;mt<2;mt++){
        int r0 = wr*32 + mt*16 + g;
        int r1 = r0 + 8;
        bool isk = (r0 < 64);
        float bi0 = isk ? bk[r0] : bv[r0-64];
        float bi1 = isk ? bk[r1] : bv[r1-64];
        #pragma unroll
        for (int n8=0;n8<4;n8++){
            int c = n0 + wc*32 + n8*8 + 2*t4;
            float v00 = acc[mt][n8][0]+bi0, v01 = acc[mt][n8][1]+bi0;
            float v10 = acc[mt][n8][2]+bi1, v11 = acc[mt][n8][3]+bi1;
            if (isk){ v00=__expf(v00); v01=__expf(v01); v10=__expf(v10); v11=__expf(v11); }
            *(__half2*)(g_kvh + ((size_t)b*128 + r0)*Nn + c) = __floats2half2_rn(v00, v01);
            *(__half2*)(g_kvh + ((size_t)b*128 + r1)*Nn + c) = __floats2half2_rn(v10, v11);
        }
    }
}

// ---------------- K2: row sums of exp(k) ----------------
__global__ void __launch_bounds__(256) rowsum_kernel()
{
    int d = blockIdx.x, b = blockIdx.y;
    const __half2* row = (const __half2*)(g_kvh + ((size_t)b*128 + d)*Nn);
    __shared__ float red[256];
    float s = 0.f;
    for (int i = threadIdx.x; i < Nn/2; i += 256){
        float2 f = __half22float2(row[i]);
        s += f.x + f.y;
    }
    red[threadIdx.x] = s; __syncthreads();
    for (int st=128; st>0; st>>=1){
        if (threadIdx.x < st) red[threadIdx.x] += red[threadIdx.x+st];
        __syncthreads();
    }
    if (threadIdx.x == 0) g_rowsum[b*KD+d] = red[0];
}

// ---------------- K3a: ctx partials via fp16 MMA ----------------
// grid (16 splits, 32 b), 128 thr. smem: ts[2][128][72] half = 36864 B (16B aligned for cp.async)
__global__ void __launch_bounds__(128) ctx_part_h()
{
    __shared__ __align__(16) __half ts[2][128][72];
    const int sp = blockIdx.x, b = blockIdx.y;
    const int tid = threadIdx.x;
    const int warp = tid>>5, lane = tid&31;
    const int g = lane>>2, t4 = lane&3;
    const size_t base = (size_t)b*128*Nn + sp*256;

    // prefetch chunk 0: 128 rows x 64 halves
    #pragma unroll
    for (int j=0;j<8;j++){
        int s = tid + 128*j;             // 0..1023
        int row = s>>3, seg = s&7;
        cpa16(&ts[0][row][seg*8], g_kvh + base + (size_t)row*Nn + seg*8);
    }
    CP_COMMIT();

    float acc[8][4];
    #pragma unroll
    for (int c=0;c<8;c++)
      #pragma unroll
      for (int k=0;k<4;k++) acc[c][k]=0.f;

    for (int ch=0; ch<4; ch++){
        if (ch+1 < 4){
            #pragma unroll
            for (int j=0;j<8;j++){
                int s = tid + 128*j;
                int row = s>>3, seg = s&7;
                cpa16(&ts[(ch+1)&1][row][seg*8],
                      g_kvh + base + (size_t)row*Nn + (ch+1)*64 + seg*8);
            }
            CP_COMMIT(); CP_WAIT1();
        } else CP_WAIT0();
        __syncthreads();
        const int buf = ch&1;
        #pragma unroll
        for (int step=0; step<4; step++){
            int kl = step*16 + t4*2;
            unsigned af[4];
            int m = warp*16 + g;
            af[0] = ldh2(&ts[buf][m][kl]);
            af[1] = ldh2(&ts[buf][m+8][kl]);
            af[2] = ldh2(&ts[buf][m][kl+8]);
            af[3] = ldh2(&ts[buf][m+8][kl+8]);
            #pragma unroll
            for (int n8=0;n8<8;n8++){
                int e = n8*8 + g;
                unsigned bf[2];
                bf[0] = ldh2(&ts[buf][64+e][kl]);
                bf[1] = ldh2(&ts[buf][64+e][kl+8]);
                mma16h(acc[n8], af, bf);
            }
        }
        __syncthreads();
    }
    float* outp = g_ctx_part + ((size_t)b*16 + sp)*KD*KD;
    #pragma unroll
    for (int n8=0;n8<8;n8++){
        int r0 = warp*16 + g;
        int c  = n8*8 + 2*t4;
        *(float2*)(outp + r0*KD + c)     = make_float2(acc[n8][0], acc[n8][1]);
        *(float2*)(outp + (r0+8)*KD + c) = make_float2(acc[n8][2], acc[n8][3]);
    }
}

// ---------------- K3b: reduce partials, divide by rowsum ----------------
__global__ void __launch_bounds__(256) ctx_reduce_kernel()
{
    int b = blockIdx.x, tid = threadIdx.x;
    for (int i = tid; i < KD*KD; i += 256) {
        int d = i >> 6;
        float s = 0.f;
        #pragma unroll
        for (int p = 0; p < 16; p++) s += g_ctx_part[((size_t)b*16+p)*KD*KD + i];
        g_ctx[(size_t)b*KD*KD + i] = s / g_rowsum[b*KD + d];
    }
}

// ---------------- K4: M = Wo folded with ctx -> half ----------------
__global__ void __launch_bounds__(256) m_kernel(const float* __restrict__ Wo)
{
    __shared__ float WoS[64*65];
    __shared__ float cS[64*65];
    int h = blockIdx.x, ot = blockIdx.y, b = blockIdx.z;
    int tid = threadIdx.x;
    int ty = tid >> 4, tx = tid & 15;
    for (int i = tid; i < 64*64; i += 256) {
        int r = i >> 6, e = i & 63;
        WoS[r*65+e] = Wo[(ot*64 + r)*QD + h*64 + e];
        cS[r*65+e]  = g_ctx[(size_t)b*KD*KD + r*64 + e];
    }
    __syncthreads();
    float acc[4][4] = {};
    #pragma unroll
    for (int e = 0; e < 64; e++) {
        float a[4], bb[4];
        #pragma unroll
        for (int i=0;i<4;i++) a[i] = WoS[(ty*4+i)*65+e];
        #pragma unroll
        for (int j=0;j<4;j++) bb[j] = cS[(tx*4+j)*65+e];
        #pragma unroll
        for (int i=0;i<4;i++)
            #pragma unroll
            for (int j=0;j<4;j++) acc[i][j] += a[i]*bb[j];
    }
    #pragma unroll
    for (int i=0;i<4;i++)
        #pragma unroll
        for (int j=0;j<4;j++)
            g_Mh[((size_t)b*OD + ot*64 + ty*4+i)*QD + h*64 + tx*4+j] = __float2half_rn(acc[i][j]);
}

// ---------------- K5: fused q-proj(fp16) -> softmax(d) -> out GEMM (fp16) ----------------
// grid (64, 32), 256 thr.
// smem: region0 = max(xs half[64][264], qs half[64][520]) = 66560 B
//       region1 = As half[2][512][40] = 81920 B  (phase C reuses as Msh [2][256][40])
// total = 148480 B
__global__ void __launch_bounds__(256) fused_q_out_mma(
    const float* __restrict__ x, const float* __restrict__ bq,
    const float* __restrict__ bo, float* __restrict__ out)
{
    extern __shared__ __half smh[];
    __half* xs  = smh;                  // [64][264] (phase A, transposed x)
    __half* qs  = smh;                  // [64][520] (phase B/C), aliases xs region
    __half* As  = smh + 33280;          // [2][512][40] phase A; [2][256][40] phase C
    const int nt = blockIdx.x, b = blockIdx.y;
    const int n0 = nt*64;
    const int tid = threadIdx.x;
    const int warp = tid>>5, lane = tid&31;
    const int g = lane>>2, t4 = lane&3;

    // x tile [256 c][64 n] -> xs[n][c] as half
    for (int i = tid; i < 256*16; i += 256) {
        int c = i>>4, n4 = (i&15)*4;
        float4 val = *(const float4*)(x + ((size_t)b*Cc + c)*Nn + n0 + n4);
        xs[(n4+0)*264 + c] = __float2half_rn(val.x);
        xs[(n4+1)*264 + c] = __float2half_rn(val.y);
        xs[(n4+2)*264 + c] = __float2half_rn(val.z);
        xs[(n4+3)*264 + c] = __float2half_rn(val.w);
    }
    // prefetch Wq chunk 0 (512 rows x 32 halves)
    #pragma unroll
    for (int j=0;j<8;j++){
        int s = tid + 256*j;             // 0..2047
        int row = s>>2, seg = s&3;
        cpa16(As + row*40 + seg*8, g_Wqh + row*Cc + seg*8);
    }
    CP_COMMIT();

    // ---- Phase A (fp16): q = Wq @ x ; warp == head, warp tile 64x64 ----
    float acc[4][8][4];
    #pragma unroll
    for (int a=0;a<4;a++)
      #pragma unroll
      for (int c=0;c<8;c++)
        #pragma unroll
        for (int k=0;k<4;k++) acc[a][c][k]=0.f;

    const int NKA = 8;    // 256 / 32
    for (int kc=0; kc<NKA; kc++){
        if (kc+1 < NKA){
            __half* dst = As + ((kc+1)&1)*20480;
            const __half* src = g_Wqh + (kc+1)*32;
            #pragma unroll
            for (int j=0;j<8;j++){
                int s = tid + 256*j;
                int row = s>>2, seg = s&3;
                cpa16(dst + row*40 + seg*8, src + row*Cc + seg*8);
            }
            CP_COMMIT(); CP_WAIT1();
        } else CP_WAIT0();
        __syncthreads();
        const __half* A0 = As + (kc&1)*20480 + (warp*64)*40;
        #pragma unroll
        for (int sub=0; sub<2; sub++){
            int kl = sub*16 + t4*2;
            int kabs = kc*32 + kl;
            unsigned bf[8][2];
            #pragma unroll
            for (int n8=0;n8<8;n8++){
                int n = n8*8 + g;
                bf[n8][0] = ldh2(xs + n*264 + kabs);
                bf[n8][1] = ldh2(xs + n*264 + kabs + 8);
            }
            #pragma unroll
            for (int mt=0;mt<4;mt++){
                const __half* Ap = A0 + (mt*16 + g)*40 + kl;
                unsigned af[4];
                af[0] = ldh2(Ap);
                af[1] = ldh2(Ap + 8*40);
                af[2] = ldh2(Ap + 8);
                af[3] = ldh2(Ap + 8*40 + 8);
                #pragma unroll
                for (int n8=0;n8<8;n8++) mma16h(acc[mt][n8], af, bf[n8]);
            }
        }
        __syncthreads();
    }

    // ---- Phase B: bias + exp + softmax over kd (this warp = one head) ----
    #pragma unroll
    for (int mt=0;mt<4;mt++){
        float b0 = bq[warp*64 + mt*16 + g];
        float b1 = bq[warp*64 + mt*16 + g + 8];
        #pragma unroll
        for (int n8=0;n8<8;n8++){
            acc[mt][n8][0] = __expf(acc[mt][n8][0] + b0);
            acc[mt][n8][1] = __expf(acc[mt][n8][1] + b0);
            acc[mt][n8][2] = __expf(acc[mt][n8][2] + b1);
            acc[mt][n8][3] = __expf(acc[mt][n8][3] + b1);
        }
    }
    float inv[8][2];
    #pragma unroll
    for (int n8=0;n8<8;n8++){
        #pragma unroll
        for (int p=0;p<2;p++){
            float s = 0.f;
            #pragma unroll
            for (int mt=0;mt<4;mt++) s += acc[mt][n8][p] + acc[mt][n8][p+2];
            s += __shfl_xor_sync(0xffffffffu, s, 4);
            s += __shfl_xor_sync(0xffffffffu, s, 8);
            s += __shfl_xor_sync(0xffffffffu, s, 16);
            inv[n8][p] = 1.f/s;
        }
    }
    __syncthreads();   // all warps done reading xs & As
    // write q_s transposed into qs[n][k] as half
    #pragma unroll
    for (int mt=0;mt<4;mt++){
        int k0 = warp*64 + mt*16 + g;
        #pragma unroll
        for (int n8=0;n8<8;n8++){
            int n = n8*8 + 2*t4;
            qs[n*520 + k0]       = __float2half_rn(acc[mt][n8][0]*inv[n8][0]);
            qs[(n+1)*520 + k0]   = __float2half_rn(acc[mt][n8][1]*inv[n8][1]);
            qs[n*520 + k0+8]     = __float2half_rn(acc[mt][n8][2]*inv[n8][0]);
            qs[(n+1)*520 + k0+8] = __float2half_rn(acc[mt][n8][3]*inv[n8][1]);
        }
    }
    __syncthreads();

    // ---- Phase C (fp16): out = M[b] @ qs ; M is 256 rows x 512 cols ----
    const __half* Mb = g_Mh + (size_t)b*OD*QD;
    __half* Msh = As;                   // [2][256][40]
    // stage k-chunk 0: 256 rows x 32 halves
    #pragma unroll
    for (int j=0;j<4;j++){
        int s = tid + 256*j;            // 0..1023
        int row = s>>2, seg = s&3;
        cpa16(Msh + row*40 + seg*8, Mb + row*QD + seg*8);
    }
    CP_COMMIT();

    float acc2[4][4][4];
    #pragma unroll
    for (int a=0;a<4;a++)
      #pragma unroll
      for (int c=0;c<4;c++)
        #pragma unroll
        for (int k=0;k<4;k++) acc2[a][c][k]=0.f;

    const int wr = warp>>1, wc = warp&1;
    const int NKC = 16;                  // 512 / 32
    for (int ki=0; ki<NKC; ki++){
        if (ki+1 < NKC){
            __half* dst = Msh + ((ki+1)&1)*10240;
            const __half* src = Mb + (ki+1)*32;
            #pragma unroll
            for (int j=0;j<4;j++){
                int s = tid + 256*j;
                int row = s>>2, seg = s&3;
                cpa16(dst + row*40 + seg*8, src + row*QD + seg*8);
            }
            CP_COMMIT(); CP_WAIT1();
        } else CP_WAIT0();
        __syncthreads();
        const __half* A0 = Msh + (ki&1)*10240 + (wr*64)*40;
        #pragma unroll
        for (int sub=0; sub<2; sub++){
            int kl = sub*16 + t4*2;
            int kabs = ki*32 + kl;
            unsigned bf[4][2];
            #pragma unroll
            for (int n8=0;n8<4;n8++){
                int n = wc*32 + n8*8 + g;
                bf[n8][0] = ldh2(qs + n*520 + kabs);
                bf[n8][1] = ldh2(qs + n*520 + kabs + 8);
            }
            #pragma unroll
            for (int mt=0;mt<4;mt++){
                const __half* Ap = A0 + (mt*16 + g)*40 + kl;
                unsigned af[4];
                af[0] = ldh2(Ap);
                af[1] = ldh2(Ap + 8*40);
                af[2] = ldh2(Ap + 8);
                af[3] = ldh2(Ap + 8*40 + 8);
                #pragma unroll
                for (int n8=0;n8<4;n8++) mma16h(acc2[mt][n8], af, bf[n8]);
            }
        }
        __syncthreads();
    }
    // epilogue
    #pragma unroll
    for (int mt=0;mt<4;mt++){
        int r0 = wr*64 + mt*16 + g;
        float bo0 = bo[r0], bo1 = bo[r0+8];
        #pragma unroll
        for (int n8=0;n8<4;n8++){
            int c = n0 + wc*32 + n8*8 + 2*t4;
            *(float2*)(out + ((size_t)b*OD + r0)*Nn + c) =
                make_float2(acc2[mt][n8][0]+bo0, acc2[mt][n8][1]+bo0);
            *(float2*)(out + ((size_t)b*OD + r0+8)*Nn + c) =
                make_float2(acc2[mt][n8][2]+bo1, acc2[mt][n8][3]+bo1);
        }
    }
}

// ---------------- launch ----------------
extern "C" void kernel_launch(void* const* d_in, const int* in_sizes, int n_in,
                              void* d_out, int out_size)
{
    const float* x  = (const float*)d_in[0];
    const float* Wq = (const float*)d_in[1];
    const float* bq = (const float*)d_in[2];
    const float* Wk = (const float*)d_in[3];
    const float* bk = (const float*)d_in[4];
    const float* Wv = (const float*)d_in[5];
    const float* bv = (const float*)d_in[6];
    const float* Wo = (const float*)d_in[7];
    const float* bo = (const float*)d_in[8];
    float* out = (float*)d_out;

    round_kernel<<<512, 256>>>(Wq, Wk, Wv);

    cudaFuncSetAttribute(kv_proj_h, cudaFuncAttributeMaxDynamicSharedMemorySize, 54272);
    kv_proj_h<<<dim3(64,32), 256, 54272>>>(x, bk, bv);

    rowsum_kernel<<<dim3(64,32), 256>>>();
    ctx_part_h<<<dim3(16,32), 128>>>();
    ctx_reduce_kernel<<<32, 256>>>();
    m_kernel<<<dim3(8,4,32), 256>>>(Wo);

    cudaFuncSetAttribute(fused_q_out_mma, cudaFuncAttributeMaxDynamicSharedMemorySize, 148480);
    fused_q_out_mma<<<dim3(64,32), 256, 148480>>>(x, bq, bo, out);
}